// round 7
// baseline (speedup 1.0000x reference)
#include <cuda_runtime.h>
#include <stdint.h>

#define NN 262144
#define NE (4*1024*1024)

// Scratch (device globals — no allocation allowed)
__device__ float g_h0[NN * 16];                 // layer-0 input, padded 9->16 (stride 16)
__device__ float g_agg[NN * 32];                // gather output (fully overwritten each layer)
__device__ float g_zpre[NN * 32];               // pre-BN MLP output
__device__ float g_cat[(size_t)NN * 128];       // JK concat; layer l output at [n*128 + l*32]
__device__ float g_stats[256];                  // per layer: [l*64+c]=sum, [l*64+32+c]=sumsq
// CSR-by-dst scratch
__device__ int g_deg[NN];
__device__ int g_off[NN + 1];
__device__ int g_pos[NN];
__device__ int g_csr[NE];
__device__ int g_bsum[256];
__device__ int g_bsum2[256];

// ---------------------------------------------------------------------------
// init: zero deg + stats, build h0 = cat(x, t, 0-pad) with stride 16
// ---------------------------------------------------------------------------
__global__ void k_init(const float* __restrict__ x, const float* __restrict__ t) {
    int i = blockIdx.x * blockDim.x + threadIdx.x;
    if (i < NN * 16) {
        int n = i >> 4, k = i & 15;
        float v = 0.f;
        if (k < 8) v = x[n * 8 + k];
        else if (k == 8) v = t[0];
        g_h0[i] = v;
    }
    if (i < NN) g_deg[i] = 0;
    if (i < 256) g_stats[i] = 0.f;
}

// ---------------------------------------------------------------------------
// CSR build: count, scan (2-level), fill
// ---------------------------------------------------------------------------
__global__ void k_count(const int* __restrict__ dst) {
    int e = blockIdx.x * blockDim.x + threadIdx.x;
    if (e < NE) atomicAdd(&g_deg[dst[e]], 1);
}

__global__ void k_scan1() {   // 256 blocks x 1024 threads: per-block exclusive scan
    __shared__ int s[1024];
    int tid = threadIdx.x;
    int i = blockIdx.x * 1024 + tid;
    int v = g_deg[i];
    s[tid] = v;
    __syncthreads();
#pragma unroll
    for (int off = 1; off < 1024; off <<= 1) {
        int tv = (tid >= off) ? s[tid - off] : 0;
        __syncthreads();
        s[tid] += tv;
        __syncthreads();
    }
    g_off[i] = s[tid] - v;                 // exclusive
    if (tid == 1023) g_bsum[blockIdx.x] = s[1023];
}

__global__ void k_scan2() {   // 1 block x 256 threads: exclusive scan of block sums
    __shared__ int s[256];
    int tid = threadIdx.x;
    int v = g_bsum[tid];
    s[tid] = v;
    __syncthreads();
#pragma unroll
    for (int off = 1; off < 256; off <<= 1) {
        int tv = (tid >= off) ? s[tid - off] : 0;
        __syncthreads();
        s[tid] += tv;
        __syncthreads();
    }
    g_bsum2[tid] = s[tid] - v;
}

__global__ void k_scan3() {
    int i = blockIdx.x * blockDim.x + threadIdx.x;
    if (i < NN) {
        int o = g_off[i] + g_bsum2[i >> 10];
        g_off[i] = o;
        g_pos[i] = o;
    }
    if (i == 0) g_off[NN] = NE;
}

__global__ void k_fill(const int* __restrict__ src, const int* __restrict__ dst) {
    int e = blockIdx.x * blockDim.x + threadIdx.x;
    if (e >= NE) return;
    int slot = atomicAdd(&g_pos[dst[e]], 1);
    g_csr[slot] = src[e];
}

// ---------------------------------------------------------------------------
// gather (layers 1..3): ONE WARP PER NODE, lane = channel.
// Each edge -> one coalesced 128B load of the source row. CSR loads are
// warp-uniform broadcasts. Accumulate in 1 reg/lane, one 128B store/node.
// HSTRIDE = source row stride in floats (128 for g_cat slices).
// ---------------------------------------------------------------------------
__global__ void __launch_bounds__(256) k_gather32(const float* __restrict__ hbase) {
    int gtid = blockIdx.x * 256 + threadIdx.x;
    int n = gtid >> 5;
    int lane = gtid & 31;
    if (n >= NN) return;
    int k = g_off[n], end = g_off[n + 1];
    float acc = 0.f;
    for (; k + 4 <= end; k += 4) {
        int s0 = g_csr[k], s1 = g_csr[k + 1], s2 = g_csr[k + 2], s3 = g_csr[k + 3];
        float v0 = hbase[(size_t)s0 * 128 + lane];
        float v1 = hbase[(size_t)s1 * 128 + lane];
        float v2 = hbase[(size_t)s2 * 128 + lane];
        float v3 = hbase[(size_t)s3 * 128 + lane];
        acc += (v0 + v1) + (v2 + v3);
    }
    for (; k < end; k++) {
        int s0 = g_csr[k];
        acc += hbase[(size_t)s0 * 128 + lane];
    }
    g_agg[(size_t)n * 32 + lane] = acc;
}

// layer-0 gather: rows are 16 floats (64B) -> two nodes per warp (half-warp each)
__global__ void __launch_bounds__(256) k_gather16() {
    int gtid = blockIdx.x * 256 + threadIdx.x;
    int n = gtid >> 4;
    int c = gtid & 15;
    if (n >= NN) return;
    int k = g_off[n], end = g_off[n + 1];
    float acc = 0.f;
    for (; k + 4 <= end; k += 4) {
        int s0 = g_csr[k], s1 = g_csr[k + 1], s2 = g_csr[k + 2], s3 = g_csr[k + 3];
        float v0 = g_h0[(size_t)s0 * 16 + c];
        float v1 = g_h0[(size_t)s1 * 16 + c];
        float v2 = g_h0[(size_t)s2 * 16 + c];
        float v3 = g_h0[(size_t)s3 * 16 + c];
        acc += (v0 + v1) + (v2 + v3);
    }
    for (; k < end; k++) {
        int s0 = g_csr[k];
        acc += g_h0[(size_t)s0 * 16 + c];
    }
    g_agg[(size_t)n * 32 + c] = acc;
}

// ---------------------------------------------------------------------------
// node MLP: z=(1+eps)h+agg; u=relu(z@W1+b1); v=u@W2+b2 -> g_zpre
// ---------------------------------------------------------------------------
template<int K, int KROWS, int HST>
__global__ void __launch_bounds__(128) k_node(
    const float* __restrict__ W1, const float* __restrict__ b1,
    const float* __restrict__ W2, const float* __restrict__ b2,
    const float* __restrict__ eps, int l)
{
    __shared__ float sW1[K * 32];
    __shared__ float sW2[32 * 32];
    __shared__ float sb1[32];
    __shared__ float sb2[32];
    int tid = threadIdx.x;
    for (int i = tid; i < K * 32; i += 128) {
        int k = i >> 5;
        sW1[i] = (k < KROWS) ? W1[i] : 0.f;
    }
    for (int i = tid; i < 1024; i += 128) sW2[i] = W2[i];
    if (tid < 32) { sb1[tid] = b1[tid]; sb2[tid] = b2[tid]; }
    __syncthreads();

    int n = blockIdx.x * 128 + tid;
    if (n >= NN) return;
    float e1 = 1.f + eps[l];
    const float* hp = (K == 12) ? (g_h0 + (size_t)n * HST)
                                : (g_cat + (size_t)n * 128 + (l - 1) * 32);
    const float* ap = g_agg + (size_t)n * 32;

    float z[K];
#pragma unroll
    for (int k = 0; k < K; k += 4) {
        float4 h4 = *(const float4*)(hp + k);
        float4 a4 = *(const float4*)(ap + k);
        z[k + 0] = fmaf(e1, h4.x, a4.x);
        z[k + 1] = fmaf(e1, h4.y, a4.y);
        z[k + 2] = fmaf(e1, h4.z, a4.z);
        z[k + 3] = fmaf(e1, h4.w, a4.w);
    }

    float u[32];
#pragma unroll
    for (int j = 0; j < 32; j++) u[j] = sb1[j];
#pragma unroll
    for (int k = 0; k < K; k++) {
        float zk = z[k];
        const float4* w = (const float4*)&sW1[k << 5];
#pragma unroll
        for (int jj = 0; jj < 8; jj++) {
            float4 wv = w[jj];
            u[4 * jj + 0] = fmaf(zk, wv.x, u[4 * jj + 0]);
            u[4 * jj + 1] = fmaf(zk, wv.y, u[4 * jj + 1]);
            u[4 * jj + 2] = fmaf(zk, wv.z, u[4 * jj + 2]);
            u[4 * jj + 3] = fmaf(zk, wv.w, u[4 * jj + 3]);
        }
    }
#pragma unroll
    for (int j = 0; j < 32; j++) u[j] = fmaxf(u[j], 0.f);

    float v[32];
#pragma unroll
    for (int j = 0; j < 32; j++) v[j] = sb2[j];
#pragma unroll
    for (int k = 0; k < 32; k++) {
        float uk = u[k];
        const float4* w = (const float4*)&sW2[k << 5];
#pragma unroll
        for (int jj = 0; jj < 8; jj++) {
            float4 wv = w[jj];
            v[4 * jj + 0] = fmaf(uk, wv.x, v[4 * jj + 0]);
            v[4 * jj + 1] = fmaf(uk, wv.y, v[4 * jj + 1]);
            v[4 * jj + 2] = fmaf(uk, wv.z, v[4 * jj + 2]);
            v[4 * jj + 3] = fmaf(uk, wv.w, v[4 * jj + 3]);
        }
    }

    float* zp = g_zpre + (size_t)n * 32;
#pragma unroll
    for (int jj = 0; jj < 8; jj++) {
        float4 o;
        o.x = v[4 * jj + 0]; o.y = v[4 * jj + 1];
        o.z = v[4 * jj + 2]; o.w = v[4 * jj + 3];
        *(float4*)(zp + 4 * jj) = o;
    }
}

// ---------------------------------------------------------------------------
// BN stats: lane c owns channel c (coalesced), shared + global atomics
// ---------------------------------------------------------------------------
__global__ void k_stats(int l) {
    int lane = threadIdx.x & 31;
    int warpId = (blockIdx.x * blockDim.x + threadIdx.x) >> 5;
    int nwarps = (gridDim.x * blockDim.x) >> 5;
    float s = 0.f, q = 0.f;
    for (int n = warpId; n < NN; n += nwarps) {
        float v = g_zpre[(size_t)n * 32 + lane];
        s += v;
        q += v * v;
    }
    __shared__ float ss[32], sq[32];
    if (threadIdx.x < 32) { ss[threadIdx.x] = 0.f; sq[threadIdx.x] = 0.f; }
    __syncthreads();
    atomicAdd(&ss[lane], s);
    atomicAdd(&sq[lane], q);
    __syncthreads();
    if (threadIdx.x < 32) {
        atomicAdd(&g_stats[l * 64 + threadIdx.x], ss[threadIdx.x]);
        atomicAdd(&g_stats[l * 64 + 32 + threadIdx.x], sq[threadIdx.x]);
    }
}

// ---------------------------------------------------------------------------
// BN + ReLU -> g_cat slice
// ---------------------------------------------------------------------------
__global__ void k_bn(const float* __restrict__ gamma, const float* __restrict__ beta, int l) {
    int i = blockIdx.x * blockDim.x + threadIdx.x;
    if (i >= NN * 32) return;
    int c = i & 31;
    const float inv = 1.0f / (float)NN;
    float mu = g_stats[l * 64 + c] * inv;
    float var = g_stats[l * 64 + 32 + c] * inv - mu * mu;
    float rs = rsqrtf(var + 1e-5f);
    float g = gamma[l * 32 + c], b = beta[l * 32 + c];
    float val = (g_zpre[i] - mu) * rs * g + b;
    val = fmaxf(val, 0.f);
    int n = i >> 5;
    g_cat[(size_t)n * 128 + l * 32 + c] = val;
}

// ---------------------------------------------------------------------------
// final: new_x = cat @ lin_W + lin_b; masked write-back into x (int32 masks)
// ---------------------------------------------------------------------------
__global__ void __launch_bounds__(128) k_final(
    const float* __restrict__ x, const float* __restrict__ linW,
    const float* __restrict__ linb,
    const int* __restrict__ nmask, const int* __restrict__ emask,
    const int* __restrict__ ondp, const int* __restrict__ oedp,
    float* __restrict__ out)
{
    __shared__ float sW[128 * 8];
    __shared__ float sb[8];
    int tid = threadIdx.x;
    for (int i = tid; i < 1024; i += 128) sW[i] = linW[i];
    if (tid < 8) sb[tid] = linb[tid];
    __syncthreads();

    int n = blockIdx.x * 128 + tid;
    if (n >= NN) return;

    float acc[8];
#pragma unroll
    for (int j = 0; j < 8; j++) acc[j] = sb[j];
    const float* cp = g_cat + (size_t)n * 128;
#pragma unroll 8
    for (int k = 0; k < 128; k += 4) {
        float4 cv = *(const float4*)(cp + k);
        float ck[4] = {cv.x, cv.y, cv.z, cv.w};
#pragma unroll
        for (int kk = 0; kk < 4; kk++) {
            const float4* w = (const float4*)&sW[(k + kk) * 8];
            float4 w0 = w[0], w1 = w[1];
            float c0 = ck[kk];
            acc[0] = fmaf(c0, w0.x, acc[0]);
            acc[1] = fmaf(c0, w0.y, acc[1]);
            acc[2] = fmaf(c0, w0.z, acc[2]);
            acc[3] = fmaf(c0, w0.w, acc[3]);
            acc[4] = fmaf(c0, w1.x, acc[4]);
            acc[5] = fmaf(c0, w1.y, acc[5]);
            acc[6] = fmaf(c0, w1.z, acc[6]);
            acc[7] = fmaf(c0, w1.w, acc[7]);
        }
    }

    int ond = ondp[0], oed = oedp[0];
    bool nm = nmask[n] != 0;
    bool em = emask[n] != 0;
#pragma unroll
    for (int j = 0; j < 8; j++) {
        bool take = (j >= 1) && ((nm && j < ond + 1) || (em && j < oed + 1));
        out[(size_t)n * 8 + j] = take ? acc[j] : x[(size_t)n * 8 + j];
    }
}

// ---------------------------------------------------------------------------
extern "C" void kernel_launch(void* const* d_in, const int* in_sizes, int n_in,
                              void* d_out, int out_size) {
    const float* x     = (const float*)d_in[0];
    const float* t     = (const float*)d_in[1];
    const int*   ei    = (const int*)d_in[2];
    const int*   nmask = (const int*)d_in[3];
    const int*   emask = (const int*)d_in[4];
    const int*   ondp  = (const int*)d_in[5];
    const int*   oedp  = (const int*)d_in[6];
    const float* W1f   = (const float*)d_in[7];
    const float* b1f   = (const float*)d_in[8];
    const float* W2f   = (const float*)d_in[9];
    const float* b2f   = (const float*)d_in[10];
    const float* W1r   = (const float*)d_in[11];
    const float* b1r   = (const float*)d_in[12];
    const float* W2r   = (const float*)d_in[13];
    const float* b2r   = (const float*)d_in[14];
    const float* eps   = (const float*)d_in[15];
    const float* gam   = (const float*)d_in[16];
    const float* bet   = (const float*)d_in[17];
    const float* linW  = (const float*)d_in[18];
    const float* linb  = (const float*)d_in[19];
    float* out = (float*)d_out;

    const int* src = ei;
    const int* dst = ei + NE;

    // init + CSR build (once per launch)
    k_init<<<(NN * 16) / 256, 256>>>(x, t);
    k_count<<<NE / 256, 256>>>(dst);
    k_scan1<<<256, 1024>>>();
    k_scan2<<<1, 256>>>();
    k_scan3<<<NN / 256, 256>>>();
    k_fill<<<NE / 256, 256>>>(src, dst);

    float* catp;  cudaGetSymbolAddress((void**)&catp, g_cat);

    // layer 0 (padded K=12, h0 stride 16; half-warp per node)
    k_gather16<<<(NN * 16) / 256, 256>>>();
    k_node<12, 9, 16><<<NN / 128, 128>>>(W1f, b1f, W2f, b2f, eps, 0);
    k_stats<<<1024, 256>>>(0);
    k_bn<<<(NN * 32) / 256, 256>>>(gam, bet, 0);

    // layers 1..3 (warp per node, coalesced 128B edge loads)
    for (int l = 1; l < 4; l++) {
        k_gather32<<<(NN * 32) / 256, 256>>>(catp + (l - 1) * 32);
        k_node<32, 32, 16><<<NN / 128, 128>>>(W1r + (l - 1) * 1024, b1r + (l - 1) * 32,
                                              W2r + (l - 1) * 1024, b2r + (l - 1) * 32,
                                              eps, l);
        k_stats<<<1024, 256>>>(l);
        k_bn<<<(NN * 32) / 256, 256>>>(gam, bet, l);
    }

    k_final<<<NN / 128, 128>>>(x, linW, linb, nmask, emask, ondp, oedp, out);
}

// round 8
// speedup vs baseline: 1.8400x; 1.8400x over previous
#include <cuda_runtime.h>
#include <stdint.h>

#define NN 262144
#define NE (4*1024*1024)

// Scratch (device globals — no allocation allowed)
__device__ float g_h0[NN * 16];                 // layer-0 input, padded 9->16 (stride 16)
__device__ float g_hl[4][NN * 32];              // DENSE per-layer outputs (32MB each, L2-resident)
__device__ float g_agg[NN * 32];                // gather output (fully overwritten each layer)
__device__ float g_zpre[NN * 32];               // pre-BN MLP output
__device__ float g_stats[256];                  // per layer: [l*64+c]=sum, [l*64+32+c]=sumsq
// CSR-by-dst scratch
__device__ int g_deg[NN];
__device__ int g_off[NN + 1];
__device__ int g_pos[NN];
__device__ int g_csr[NE];
__device__ int g_bsum[256];
__device__ int g_bsum2[256];

// ---------------------------------------------------------------------------
// init: zero deg + stats, build h0 = cat(x, t, 0-pad) with stride 16
// ---------------------------------------------------------------------------
__global__ void k_init(const float* __restrict__ x, const float* __restrict__ t) {
    int i = blockIdx.x * blockDim.x + threadIdx.x;
    if (i < NN * 16) {
        int n = i >> 4, k = i & 15;
        float v = 0.f;
        if (k < 8) v = x[n * 8 + k];
        else if (k == 8) v = t[0];
        g_h0[i] = v;
    }
    if (i < NN) g_deg[i] = 0;
    if (i < 256) g_stats[i] = 0.f;
}

// ---------------------------------------------------------------------------
// CSR build: count, scan (2-level), fill
// ---------------------------------------------------------------------------
__global__ void k_count(const int* __restrict__ dst) {
    int e = blockIdx.x * blockDim.x + threadIdx.x;
    if (e < NE) atomicAdd(&g_deg[dst[e]], 1);
}

__global__ void k_scan1() {   // 256 blocks x 1024 threads: per-block exclusive scan
    __shared__ int s[1024];
    int tid = threadIdx.x;
    int i = blockIdx.x * 1024 + tid;
    int v = g_deg[i];
    s[tid] = v;
    __syncthreads();
#pragma unroll
    for (int off = 1; off < 1024; off <<= 1) {
        int tv = (tid >= off) ? s[tid - off] : 0;
        __syncthreads();
        s[tid] += tv;
        __syncthreads();
    }
    g_off[i] = s[tid] - v;                 // exclusive
    if (tid == 1023) g_bsum[blockIdx.x] = s[1023];
}

__global__ void k_scan2() {   // 1 block x 256 threads: exclusive scan of block sums
    __shared__ int s[256];
    int tid = threadIdx.x;
    int v = g_bsum[tid];
    s[tid] = v;
    __syncthreads();
#pragma unroll
    for (int off = 1; off < 256; off <<= 1) {
        int tv = (tid >= off) ? s[tid - off] : 0;
        __syncthreads();
        s[tid] += tv;
        __syncthreads();
    }
    g_bsum2[tid] = s[tid] - v;
}

__global__ void k_scan3() {
    int i = blockIdx.x * blockDim.x + threadIdx.x;
    if (i < NN) {
        int o = g_off[i] + g_bsum2[i >> 10];
        g_off[i] = o;
        g_pos[i] = o;
    }
    if (i == 0) g_off[NN] = NE;
}

__global__ void k_fill(const int* __restrict__ src, const int* __restrict__ dst) {
    int e = blockIdx.x * blockDim.x + threadIdx.x;
    if (e >= NE) return;
    int slot = atomicAdd(&g_pos[dst[e]], 1);
    g_csr[slot] = src[e];
}

// ---------------------------------------------------------------------------
// gather: chunk-per-thread (R6 layout — sector-perfect: 8 adjacent lanes of a
// node cover one full 128B source row in lockstep). SHIFT=log2(chunks),
// ST = dense source row stride in floats.
// ---------------------------------------------------------------------------
template<int SHIFT, int ST>
__global__ void __launch_bounds__(256) k_gather(const float* __restrict__ hbase) {
    int idx = blockIdx.x * blockDim.x + threadIdx.x;
    int n = idx >> SHIFT;
    int c = idx & ((1 << SHIFT) - 1);
    if (n >= NN) return;
    int k = g_off[n], end = g_off[n + 1];
    float ax = 0.f, ay = 0.f, az = 0.f, aw = 0.f;
    for (; k + 4 <= end; k += 4) {
        int s0 = g_csr[k], s1 = g_csr[k + 1], s2 = g_csr[k + 2], s3 = g_csr[k + 3];
        float4 v0 = *(const float4*)(hbase + (size_t)s0 * ST + c * 4);
        float4 v1 = *(const float4*)(hbase + (size_t)s1 * ST + c * 4);
        float4 v2 = *(const float4*)(hbase + (size_t)s2 * ST + c * 4);
        float4 v3 = *(const float4*)(hbase + (size_t)s3 * ST + c * 4);
        ax += (v0.x + v1.x) + (v2.x + v3.x);
        ay += (v0.y + v1.y) + (v2.y + v3.y);
        az += (v0.z + v1.z) + (v2.z + v3.z);
        aw += (v0.w + v1.w) + (v2.w + v3.w);
    }
    for (; k < end; k++) {
        int s0 = g_csr[k];
        float4 v0 = *(const float4*)(hbase + (size_t)s0 * ST + c * 4);
        ax += v0.x; ay += v0.y; az += v0.z; aw += v0.w;
    }
    float4 o; o.x = ax; o.y = ay; o.z = az; o.w = aw;
    *(float4*)(g_agg + (size_t)n * 32 + c * 4) = o;
}

// ---------------------------------------------------------------------------
// node MLP: z=(1+eps)h+agg; u=relu(z@W1+b1); v=u@W2+b2 -> g_zpre
// hprev is a dense buffer with row stride HST.
// ---------------------------------------------------------------------------
template<int K, int KROWS, int HST>
__global__ void __launch_bounds__(128) k_node(
    const float* __restrict__ hprev,
    const float* __restrict__ W1, const float* __restrict__ b1,
    const float* __restrict__ W2, const float* __restrict__ b2,
    const float* __restrict__ eps, int l)
{
    __shared__ float sW1[K * 32];
    __shared__ float sW2[32 * 32];
    __shared__ float sb1[32];
    __shared__ float sb2[32];
    int tid = threadIdx.x;
    for (int i = tid; i < K * 32; i += 128) {
        int k = i >> 5;
        sW1[i] = (k < KROWS) ? W1[i] : 0.f;
    }
    for (int i = tid; i < 1024; i += 128) sW2[i] = W2[i];
    if (tid < 32) { sb1[tid] = b1[tid]; sb2[tid] = b2[tid]; }
    __syncthreads();

    int n = blockIdx.x * 128 + tid;
    if (n >= NN) return;
    float e1 = 1.f + eps[l];
    const float* hp = hprev + (size_t)n * HST;
    const float* ap = g_agg + (size_t)n * 32;

    float z[K];
#pragma unroll
    for (int k = 0; k < K; k += 4) {
        float4 h4 = *(const float4*)(hp + k);
        float4 a4 = *(const float4*)(ap + k);
        z[k + 0] = fmaf(e1, h4.x, a4.x);
        z[k + 1] = fmaf(e1, h4.y, a4.y);
        z[k + 2] = fmaf(e1, h4.z, a4.z);
        z[k + 3] = fmaf(e1, h4.w, a4.w);
    }

    float u[32];
#pragma unroll
    for (int j = 0; j < 32; j++) u[j] = sb1[j];
#pragma unroll
    for (int k = 0; k < K; k++) {
        float zk = z[k];
        const float4* w = (const float4*)&sW1[k << 5];
#pragma unroll
        for (int jj = 0; jj < 8; jj++) {
            float4 wv = w[jj];
            u[4 * jj + 0] = fmaf(zk, wv.x, u[4 * jj + 0]);
            u[4 * jj + 1] = fmaf(zk, wv.y, u[4 * jj + 1]);
            u[4 * jj + 2] = fmaf(zk, wv.z, u[4 * jj + 2]);
            u[4 * jj + 3] = fmaf(zk, wv.w, u[4 * jj + 3]);
        }
    }
#pragma unroll
    for (int j = 0; j < 32; j++) u[j] = fmaxf(u[j], 0.f);

    float v[32];
#pragma unroll
    for (int j = 0; j < 32; j++) v[j] = sb2[j];
#pragma unroll
    for (int k = 0; k < 32; k++) {
        float uk = u[k];
        const float4* w = (const float4*)&sW2[k << 5];
#pragma unroll
        for (int jj = 0; jj < 8; jj++) {
            float4 wv = w[jj];
            v[4 * jj + 0] = fmaf(uk, wv.x, v[4 * jj + 0]);
            v[4 * jj + 1] = fmaf(uk, wv.y, v[4 * jj + 1]);
            v[4 * jj + 2] = fmaf(uk, wv.z, v[4 * jj + 2]);
            v[4 * jj + 3] = fmaf(uk, wv.w, v[4 * jj + 3]);
        }
    }

    float* zp = g_zpre + (size_t)n * 32;
#pragma unroll
    for (int jj = 0; jj < 8; jj++) {
        float4 o;
        o.x = v[4 * jj + 0]; o.y = v[4 * jj + 1];
        o.z = v[4 * jj + 2]; o.w = v[4 * jj + 3];
        *(float4*)(zp + 4 * jj) = o;
    }
}

// ---------------------------------------------------------------------------
// BN stats: lane c owns channel c (coalesced), shared + global atomics
// ---------------------------------------------------------------------------
__global__ void k_stats(int l) {
    int lane = threadIdx.x & 31;
    int warpId = (blockIdx.x * blockDim.x + threadIdx.x) >> 5;
    int nwarps = (gridDim.x * blockDim.x) >> 5;
    float s = 0.f, q = 0.f;
    for (int n = warpId; n < NN; n += nwarps) {
        float v = g_zpre[(size_t)n * 32 + lane];
        s += v;
        q += v * v;
    }
    __shared__ float ss[32], sq[32];
    if (threadIdx.x < 32) { ss[threadIdx.x] = 0.f; sq[threadIdx.x] = 0.f; }
    __syncthreads();
    atomicAdd(&ss[lane], s);
    atomicAdd(&sq[lane], q);
    __syncthreads();
    if (threadIdx.x < 32) {
        atomicAdd(&g_stats[l * 64 + threadIdx.x], ss[threadIdx.x]);
        atomicAdd(&g_stats[l * 64 + 32 + threadIdx.x], sq[threadIdx.x]);
    }
}

// ---------------------------------------------------------------------------
// BN + ReLU -> dense layer output buffer
// ---------------------------------------------------------------------------
__global__ void k_bn(const float* __restrict__ gamma, const float* __restrict__ beta, int l) {
    int i = blockIdx.x * blockDim.x + threadIdx.x;
    if (i >= NN * 32) return;
    int c = i & 31;
    const float inv = 1.0f / (float)NN;
    float mu = g_stats[l * 64 + c] * inv;
    float var = g_stats[l * 64 + 32 + c] * inv - mu * mu;
    float rs = rsqrtf(var + 1e-5f);
    float g = gamma[l * 32 + c], b = beta[l * 32 + c];
    float val = (g_zpre[i] - mu) * rs * g + b;
    g_hl[l][i] = fmaxf(val, 0.f);
}

// ---------------------------------------------------------------------------
// final: new_x = cat(h0..h3) @ lin_W + lin_b; masked write-back (int32 masks)
// ---------------------------------------------------------------------------
__global__ void __launch_bounds__(128) k_final(
    const float* __restrict__ x, const float* __restrict__ linW,
    const float* __restrict__ linb,
    const int* __restrict__ nmask, const int* __restrict__ emask,
    const int* __restrict__ ondp, const int* __restrict__ oedp,
    float* __restrict__ out)
{
    __shared__ float sW[128 * 8];
    __shared__ float sb[8];
    int tid = threadIdx.x;
    for (int i = tid; i < 1024; i += 128) sW[i] = linW[i];
    if (tid < 8) sb[tid] = linb[tid];
    __syncthreads();

    int n = blockIdx.x * 128 + tid;
    if (n >= NN) return;

    float acc[8];
#pragma unroll
    for (int j = 0; j < 8; j++) acc[j] = sb[j];
#pragma unroll
    for (int l = 0; l < 4; l++) {
        const float* cp = &g_hl[l][(size_t)n * 32];
#pragma unroll 8
        for (int k = 0; k < 32; k += 4) {
            float4 cv = *(const float4*)(cp + k);
            float ck[4] = {cv.x, cv.y, cv.z, cv.w};
#pragma unroll
            for (int kk = 0; kk < 4; kk++) {
                const float4* w = (const float4*)&sW[(l * 32 + k + kk) * 8];
                float4 w0 = w[0], w1 = w[1];
                float c0 = ck[kk];
                acc[0] = fmaf(c0, w0.x, acc[0]);
                acc[1] = fmaf(c0, w0.y, acc[1]);
                acc[2] = fmaf(c0, w0.z, acc[2]);
                acc[3] = fmaf(c0, w0.w, acc[3]);
                acc[4] = fmaf(c0, w1.x, acc[4]);
                acc[5] = fmaf(c0, w1.y, acc[5]);
                acc[6] = fmaf(c0, w1.z, acc[6]);
                acc[7] = fmaf(c0, w1.w, acc[7]);
            }
        }
    }

    int ond = ondp[0], oed = oedp[0];
    bool nm = nmask[n] != 0;
    bool em = emask[n] != 0;
#pragma unroll
    for (int j = 0; j < 8; j++) {
        bool take = (j >= 1) && ((nm && j < ond + 1) || (em && j < oed + 1));
        out[(size_t)n * 8 + j] = take ? acc[j] : x[(size_t)n * 8 + j];
    }
}

// ---------------------------------------------------------------------------
extern "C" void kernel_launch(void* const* d_in, const int* in_sizes, int n_in,
                              void* d_out, int out_size) {
    const float* x     = (const float*)d_in[0];
    const float* t     = (const float*)d_in[1];
    const int*   ei    = (const int*)d_in[2];
    const int*   nmask = (const int*)d_in[3];
    const int*   emask = (const int*)d_in[4];
    const int*   ondp  = (const int*)d_in[5];
    const int*   oedp  = (const int*)d_in[6];
    const float* W1f   = (const float*)d_in[7];
    const float* b1f   = (const float*)d_in[8];
    const float* W2f   = (const float*)d_in[9];
    const float* b2f   = (const float*)d_in[10];
    const float* W1r   = (const float*)d_in[11];
    const float* b1r   = (const float*)d_in[12];
    const float* W2r   = (const float*)d_in[13];
    const float* b2r   = (const float*)d_in[14];
    const float* eps   = (const float*)d_in[15];
    const float* gam   = (const float*)d_in[16];
    const float* bet   = (const float*)d_in[17];
    const float* linW  = (const float*)d_in[18];
    const float* linb  = (const float*)d_in[19];
    float* out = (float*)d_out;

    const int* src = ei;
    const int* dst = ei + NE;

    // init + CSR build (once per launch)
    k_init<<<(NN * 16) / 256, 256>>>(x, t);
    k_count<<<NE / 256, 256>>>(dst);
    k_scan1<<<256, 1024>>>();
    k_scan2<<<1, 256>>>();
    k_scan3<<<NN / 256, 256>>>();
    k_fill<<<NE / 256, 256>>>(src, dst);

    float* h0p;  cudaGetSymbolAddress((void**)&h0p, g_h0);
    float* hlp;  cudaGetSymbolAddress((void**)&hlp, g_hl);

    // layer 0 (padded K=12, h0 stride 16; 4 chunk-threads per node)
    k_gather<2, 16><<<(NN * 4) / 256, 256>>>(h0p);
    k_node<12, 9, 16><<<NN / 128, 128>>>(h0p, W1f, b1f, W2f, b2f, eps, 0);
    k_stats<<<1024, 256>>>(0);
    k_bn<<<(NN * 32) / 256, 256>>>(gam, bet, 0);

    // layers 1..3 (dense 32-float rows; 8 chunk-threads per node)
    for (int l = 1; l < 4; l++) {
        const float* hprev = hlp + (size_t)(l - 1) * NN * 32;
        k_gather<3, 32><<<(NN * 8) / 256, 256>>>(hprev);
        k_node<32, 32, 32><<<NN / 128, 128>>>(hprev,
                                              W1r + (l - 1) * 1024, b1r + (l - 1) * 32,
                                              W2r + (l - 1) * 1024, b2r + (l - 1) * 32,
                                              eps, l);
        k_stats<<<1024, 256>>>(l);
        k_bn<<<(NN * 32) / 256, 256>>>(gam, bet, l);
    }

    k_final<<<NN / 128, 128>>>(x, linW, linb, nmask, emask, ondp, oedp, out);
}